// round 2
// baseline (speedup 1.0000x reference)
#include <cuda_runtime.h>
#include <math.h>

#define T_LEN 8192
#define HALF  4096
#define CH    128
#define BATCH 16
#define NSIG  (BATCH * CH)
#define KSPLIT 8
#define KSEG  (T_LEN / KSPLIT)   // 1024
#define BK    16
#define SPAD  66                 // padded row length for smem tiles

// Scratch (alloc-free rule: __device__ globals)
__device__ float2 g_z[NSIG * T_LEN];                      // unit analytic signal (cos,sin) : 128 MB
__device__ float2 g_part[KSPLIT * BATCH * CH * CH];       // K-split partial (re,im)        : 16 MB

// ---------------------------------------------------------------------------
// Kernel 1: per-signal FFT -> mask (zero freqs >= T/2) -> IFFT -> normalize.
// Forward radix-2 DIF (natural in, bit-reversed out). Mask in bit-reversed
// order == zero odd positions. Inverse radix-2 DIT (bit-reversed in, natural
// out). 1/N scale skipped (cancelled by unit normalization).
// ---------------------------------------------------------------------------
extern __shared__ float2 s_fft[];   // [0..8191]=data, [8192..12287]=twiddles

__global__ void __launch_bounds__(512) fft_kernel(const float* __restrict__ x) {
    float2* d  = s_fft;
    float2* tw = s_fft + T_LEN;
    const int tid = threadIdx.x;
    const int base = blockIdx.x * T_LEN;

    // Load real input as complex
    for (int t = tid; t < T_LEN; t += 512)
        d[t] = make_float2(x[base + t], 0.0f);
    // Twiddle table: tw[t] = exp(-2*pi*i*t/N)
    for (int t = tid; t < HALF; t += 512) {
        float s, c;
        sincosf(-6.283185307179586e0f * (float)t / (float)T_LEN, &s, &c);
        tw[t] = make_float2(c, s);
    }
    __syncthreads();

    // Forward DIF
    for (int m = HALF; m >= 1; m >>= 1) {
        const int twmul = HALF / m;
        for (int u = tid; u < HALF; u += 512) {
            const int j  = u & (m - 1);
            const int i0 = ((u - j) << 1) + j;   // (u/m)*2m + j
            const int i1 = i0 + m;
            float2 a = d[i0], b = d[i1];
            float2 w = tw[j * twmul];
            float2 s = make_float2(a.x - b.x, a.y - b.y);
            d[i0] = make_float2(a.x + b.x, a.y + b.y);
            d[i1] = make_float2(s.x * w.x - s.y * w.y, s.x * w.y + s.y * w.x);
        }
        __syncthreads();
    }

    // Mask: position p holds X[bitrev(p)]; k >= T/2 <=> p odd.
    for (int t = tid; t < T_LEN; t += 512)
        if (t & 1) d[t] = make_float2(0.0f, 0.0f);
    __syncthreads();

    // Inverse DIT (conjugate twiddles), bit-reversed input -> natural output
    for (int m = 1; m <= HALF; m <<= 1) {
        const int twmul = HALF / m;
        for (int u = tid; u < HALF; u += 512) {
            const int j  = u & (m - 1);
            const int i0 = ((u - j) << 1) + j;
            const int i1 = i0 + m;
            float2 a = d[i0], b = d[i1];
            float2 w = tw[j * twmul];            // use conj(w)
            float2 t2 = make_float2(b.x * w.x + b.y * w.y,
                                    b.y * w.x - b.x * w.y);
            d[i0] = make_float2(a.x + t2.x, a.y + t2.y);
            d[i1] = make_float2(a.x - t2.x, a.y - t2.y);
        }
        __syncthreads();
    }

    // Normalize to unit magnitude: u = xa/|xa| (== (cos(phase), sin(phase)))
    for (int t = tid; t < T_LEN; t += 512) {
        float2 v = d[t];
        float m2 = v.x * v.x + v.y * v.y;
        float2 u;
        if (m2 > 0.0f) {
            float inv = rsqrtf(m2);
            u = make_float2(v.x * inv, v.y * inv);
        } else {
            u = make_float2(1.0f, 0.0f);         // atan2(0,0)=0 -> (cos,sin)=(1,0)
        }
        g_z[base + t] = u;
    }
}

// ---------------------------------------------------------------------------
// Kernel 2: batched complex Gram partials.
// G_ij = sum_t z_i(t) * conj(z_j(t)).  64x64 output tile per block, 4x4 per
// thread, K split into 8 segments (blockIdx.x). Only upper tiles (ti<=tj).
// ---------------------------------------------------------------------------
__global__ void __launch_bounds__(256) gram_kernel() {
    __shared__ float2 As[BK][SPAD];
    __shared__ float2 Bs[BK][SPAD];

    const int b    = blockIdx.z;                 // batch
    const int tile = blockIdx.y;                 // 0:(0,0) 1:(0,1) 2:(1,1)
    const int ti   = (tile == 2) ? 1 : 0;
    const int tj   = (tile == 0) ? 0 : 1;
    const int ks   = blockIdx.x;                 // K split 0..7
    const int tid  = threadIdx.x;

    const int kk = tid & 15;                     // loader: k within tile
    const int r0 = tid >> 4;                     // loader: row group
    const int tx = tid & 15;                     // compute: j quad
    const int ty = tid >> 4;                     // compute: i quad

    const float2* __restrict__ zb = g_z + b * (CH * T_LEN);

    float re[4][4] = {{0}}, im[4][4] = {{0}};

    const int k0 = ks * KSEG;
    for (int kt = 0; kt < KSEG; kt += BK) {
        const int kg = k0 + kt + kk;
#pragma unroll
        for (int p = 0; p < 4; p++) {
            const int row = r0 + p * 16;
            As[kk][row] = zb[(ti * 64 + row) * T_LEN + kg];
            Bs[kk][row] = zb[(tj * 64 + row) * T_LEN + kg];
        }
        __syncthreads();
#pragma unroll
        for (int k = 0; k < BK; k++) {
            float2 a[4], bb[4];
#pragma unroll
            for (int q = 0; q < 4; q++) a[q]  = As[k][ty * 4 + q];
#pragma unroll
            for (int q = 0; q < 4; q++) bb[q] = Bs[k][tx * 4 + q];
#pragma unroll
            for (int qi = 0; qi < 4; qi++)
#pragma unroll
                for (int qj = 0; qj < 4; qj++) {
                    re[qi][qj] += a[qi].x * bb[qj].x + a[qi].y * bb[qj].y;
                    im[qi][qj] += a[qi].y * bb[qj].x - a[qi].x * bb[qj].y;
                }
        }
        __syncthreads();
    }

    float2* __restrict__ P = g_part + (ks * BATCH + b) * (CH * CH);
#pragma unroll
    for (int qi = 0; qi < 4; qi++) {
        const int i = ti * 64 + ty * 4 + qi;
#pragma unroll
        for (int qj = 0; qj < 4; qj++) {
            const int j = tj * 64 + tx * 4 + qj;
            P[i * CH + j] = make_float2(re[qi][qj], im[qi][qj]);
        }
    }
}

// ---------------------------------------------------------------------------
// Kernel 3: reduce K-split partials, PLV = |G|/T, mirror to lower triangle.
// ---------------------------------------------------------------------------
__global__ void finalize_kernel(float* __restrict__ out) {
    const int idx = blockIdx.x * blockDim.x + threadIdx.x;
    if (idx >= BATCH * CH * CH) return;
    const int b  = idx >> 14;
    const int ij = idx & 16383;
    const int i  = ij >> 7;
    const int j  = ij & 127;
    if (i > j) return;                           // upper triangle computes both
    float re = 0.0f, imv = 0.0f;
#pragma unroll
    for (int s = 0; s < KSPLIT; s++) {
        float2 g = g_part[(s * BATCH + b) * (CH * CH) + ij];
        re += g.x; imv += g.y;
    }
    const float plv = sqrtf(re * re + imv * imv) * (1.0f / (float)T_LEN);
    out[(b << 14) + (i << 7) + j] = plv;
    out[(b << 14) + (j << 7) + i] = plv;
}

// ---------------------------------------------------------------------------
extern "C" void kernel_launch(void* const* d_in, const int* in_sizes, int n_in,
                              void* d_out, int out_size) {
    const float* x = (const float*)d_in[0];
    float* out = (float*)d_out;

    const int smem_bytes = (T_LEN + HALF) * (int)sizeof(float2); // 96 KB
    cudaFuncSetAttribute(fft_kernel, cudaFuncAttributeMaxDynamicSharedMemorySize,
                         smem_bytes);

    fft_kernel<<<NSIG, 512, smem_bytes>>>(x);
    gram_kernel<<<dim3(KSPLIT, 3, BATCH), 256>>>();
    finalize_kernel<<<(BATCH * CH * CH + 255) / 256, 256>>>(out);
}

// round 3
// speedup vs baseline: 1.8958x; 1.8958x over previous
#include <cuda_runtime.h>
#include <math.h>

#define T_LEN 8192
#define HALF  4096
#define CH    128
#define BATCH 16
#define NSIG  (BATCH * CH)
#define KSPLIT 8
#define KSEG  (T_LEN / KSPLIT)   // 1024
#define BK    16
#define SPAD  66

// Scratch (alloc-free rule: __device__ globals)
__device__ float2 g_z[NSIG * T_LEN];                 // unit analytic signal: 128 MB
__device__ float2 g_part[KSPLIT * BATCH * CH * CH];  // K-split partials:     16 MB

// ---------------------------------------------------------------------------
// FFT kernel: register-resident radix-2, 4 stages per register group,
// 6 swizzled shared exchanges total (fwd 13 stages + mask + inv 13 stages).
// ---------------------------------------------------------------------------
__device__ __forceinline__ int swz(int i) { return i ^ ((i >> 5) & 31); }

// In-register radix-2 stages. Thread owns 16 elements idx = base + r*2^P,
// r = 0..15 (idx bits P+3..P). Does stages s = P+lb for lb in [LBLO, LBHI].
// FWD=1: DIF butterfly (a+b, (a-b)*w); FWD=0: DIT inverse ((a + b*conj(w)), (a - b*conj(w))).
template<int P, int FWD, int LBLO, int LBHI>
__device__ __forceinline__ void stages(float2 v[16], int base, const float2* __restrict__ tw) {
#pragma unroll
    for (int t = 0; t <= LBHI - LBLO; t++) {
        const int lb = FWD ? (LBHI - t) : (LBLO + t);
        const int s  = P + lb;
        const int m  = 1 << s;
        const int bm = base & (m - 1);
#pragma unroll
        for (int rr = 0; rr < 16; rr++) {
            if ((rr >> lb) & 1) continue;
            const int r1 = rr | (1 << lb);
            const int j  = bm + ((rr & ((1 << lb) - 1)) << P);
            const float2 w = tw[j << (12 - s)];
            float2 a = v[rr], b = v[r1];
            if (FWD) {
                v[rr] = make_float2(a.x + b.x, a.y + b.y);
                float2 d = make_float2(a.x - b.x, a.y - b.y);
                v[r1] = make_float2(d.x * w.x - d.y * w.y, d.x * w.y + d.y * w.x);
            } else {
                float2 tt = make_float2(b.x * w.x + b.y * w.y, b.y * w.x - b.x * w.y);
                v[rr] = make_float2(a.x + tt.x, a.y + tt.y);
                v[r1] = make_float2(a.x - tt.x, a.y - tt.y);
            }
        }
    }
}

extern __shared__ float2 smm[];   // [0..8191]=exchange buffer, [8192..12287]=twiddles

__global__ void __launch_bounds__(512) fft_kernel(const float* __restrict__ x) {
    float2* sm = smm;
    float2* tw = smm + T_LEN;
    const int tid = threadIdx.x;
    const long long gbase = (long long)blockIdx.x * T_LEN;

    // Twiddle table tw[t] = exp(-2*pi*i*t/N)
    for (int t = tid; t < HALF; t += 512) {
        float s, c;
        sincosf(-6.283185307179586e0f * (float)t / (float)T_LEN, &s, &c);
        tw[t] = make_float2(c, s);
    }

    // Ownership bases: idx = base + r * 2^P
    const int baseA = tid;                                  // P=9 (bits 12..9)
    const int baseB = ((tid >> 5) << 9) + (tid & 31);       // P=5 (bits 8..5)
    const int baseC = ((tid >> 1) << 5) + (tid & 1);        // P=1 (bits 4..1)
    const int baseD = tid << 4;                             // P=0 (bits 3..0)
    const int baseE = ((tid >> 4) << 8) + (tid & 15);       // P=4 (bits 7..4)
    const int baseF = ((tid >> 8) << 12) + (tid & 255);     // P=8 (bits 11..8)

    float2 v[16];
#pragma unroll
    for (int r = 0; r < 16; r++)
        v[r] = make_float2(x[gbase + tid + r * 512], 0.0f);
    __syncthreads();   // tw ready

    // ---- forward DIF ----
    stages<9, 1, 0, 3>(v, baseA, tw);                       // s = 12..9
#pragma unroll
    for (int r = 0; r < 16; r++) sm[swz(baseA + (r << 9))] = v[r];
    __syncthreads();
#pragma unroll
    for (int r = 0; r < 16; r++) v[r] = sm[swz(baseB + (r << 5))];
    __syncthreads();

    stages<5, 1, 0, 3>(v, baseB, tw);                       // s = 8..5
#pragma unroll
    for (int r = 0; r < 16; r++) sm[swz(baseB + (r << 5))] = v[r];
    __syncthreads();
#pragma unroll
    for (int r = 0; r < 16; r++) v[r] = sm[swz(baseC + (r << 1))];
    __syncthreads();

    stages<1, 1, 0, 3>(v, baseC, tw);                       // s = 4..1
#pragma unroll
    for (int r = 0; r < 16; r++) sm[swz(baseC + (r << 1))] = v[r];
    __syncthreads();
#pragma unroll
    for (int r = 0; r < 16; r++) v[r] = sm[swz(baseD + r)];
    __syncthreads();

    // Fused: forward stage s=0 (w=1) + mask(odd bit-reversed pos) + inverse s=0 (b=0).
    // even: a+b survives; odd zeroed; inverse s=0 copies even into odd.
#pragma unroll
    for (int r = 0; r < 16; r += 2) {
        float2 s0 = make_float2(v[r].x + v[r + 1].x, v[r].y + v[r + 1].y);
        v[r] = s0; v[r + 1] = s0;
    }

    // ---- inverse DIT ----
    stages<0, 0, 1, 3>(v, baseD, tw);                       // s = 1..3
#pragma unroll
    for (int r = 0; r < 16; r++) sm[swz(baseD + r)] = v[r];
    __syncthreads();
#pragma unroll
    for (int r = 0; r < 16; r++) v[r] = sm[swz(baseE + (r << 4))];
    __syncthreads();

    stages<4, 0, 0, 3>(v, baseE, tw);                       // s = 4..7
#pragma unroll
    for (int r = 0; r < 16; r++) sm[swz(baseE + (r << 4))] = v[r];
    __syncthreads();
#pragma unroll
    for (int r = 0; r < 16; r++) v[r] = sm[swz(baseF + (r << 8))];
    __syncthreads();

    stages<8, 0, 0, 3>(v, baseF, tw);                       // s = 8..11
#pragma unroll
    for (int r = 0; r < 16; r++) sm[swz(baseF + (r << 8))] = v[r];
    __syncthreads();
#pragma unroll
    for (int r = 0; r < 16; r++) v[r] = sm[swz(baseA + (r << 9))];
    __syncthreads();

    stages<9, 0, 3, 3>(v, baseA, tw);                       // s = 12

    // Normalize to unit magnitude and store (natural order, coalesced)
#pragma unroll
    for (int r = 0; r < 16; r++) {
        float2 u = v[r];
        float m2 = u.x * u.x + u.y * u.y;
        float2 o;
        if (m2 > 0.0f) {
            float inv = rsqrtf(m2);
            o = make_float2(u.x * inv, u.y * inv);
        } else {
            o = make_float2(1.0f, 0.0f);
        }
        g_z[gbase + tid + r * 512] = o;
    }
}

// ---------------------------------------------------------------------------
// Gram kernel with packed f32x2 FMA: acc = (re, im) per output element.
// ---------------------------------------------------------------------------
typedef unsigned long long ull;

__device__ __forceinline__ ull pack2(float lo, float hi) {
    ull r; asm("mov.b64 %0, {%1, %2};" : "=l"(r) : "f"(lo), "f"(hi)); return r;
}
__device__ __forceinline__ void fma2(ull& acc, ull a, ull b) {
    asm("fma.rn.f32x2 %0, %1, %2, %0;" : "+l"(acc) : "l"(a), "l"(b));
}
__device__ __forceinline__ void unpack2(ull p, float& lo, float& hi) {
    asm("mov.b64 {%0, %1}, %2;" : "=f"(lo), "=f"(hi) : "l"(p));
}

__global__ void __launch_bounds__(256) gram_kernel() {
    __shared__ float2 As[BK][SPAD];
    __shared__ float2 Bs[BK][SPAD];

    const int b    = blockIdx.z;
    const int tile = blockIdx.y;              // 0:(0,0) 1:(0,1) 2:(1,1)
    const int ti   = (tile == 2) ? 1 : 0;
    const int tj   = (tile == 0) ? 0 : 1;
    const int ks   = blockIdx.x;
    const int tid  = threadIdx.x;

    const int kk = tid & 15;
    const int r0 = tid >> 4;
    const int tx = tid & 15;
    const int ty = tid >> 4;

    const float2* __restrict__ zb = g_z + (long long)b * (CH * T_LEN);

    ull acc[4][4];
#pragma unroll
    for (int i = 0; i < 4; i++)
#pragma unroll
        for (int j = 0; j < 4; j++) acc[i][j] = pack2(0.0f, 0.0f);

    const int k0 = ks * KSEG;
    for (int kt = 0; kt < KSEG; kt += BK) {
        const int kg = k0 + kt + kk;
#pragma unroll
        for (int p = 0; p < 4; p++) {
            const int row = r0 + p * 16;
            As[kk][row] = zb[(long long)(ti * 64 + row) * T_LEN + kg];
            Bs[kk][row] = zb[(long long)(tj * 64 + row) * T_LEN + kg];
        }
        __syncthreads();
#pragma unroll
        for (int k = 0; k < BK; k++) {
            ull bx2[4], by2[4];
#pragma unroll
            for (int q = 0; q < 4; q++) {
                float2 bb = Bs[k][tx * 4 + q];
                bx2[q] = pack2(bb.x, bb.x);
                by2[q] = pack2(bb.y, bb.y);
            }
#pragma unroll
            for (int qi = 0; qi < 4; qi++) {
                float2 a = As[k][ty * 4 + qi];
                ull axy = pack2(a.x, a.y);      // (a.x, a.y)
                ull anx = pack2(a.y, -a.x);     // (a.y, -a.x)
#pragma unroll
                for (int qj = 0; qj < 4; qj++) {
                    fma2(acc[qi][qj], axy, bx2[qj]);  // (+ax*bx, +ay*bx)
                    fma2(acc[qi][qj], anx, by2[qj]);  // (+ay*by, -ax*by)
                }
            }
        }
        __syncthreads();
    }

    float2* __restrict__ P = g_part + (long long)(ks * BATCH + b) * (CH * CH);
#pragma unroll
    for (int qi = 0; qi < 4; qi++) {
        const int i = ti * 64 + ty * 4 + qi;
#pragma unroll
        for (int qj = 0; qj < 4; qj++) {
            const int j = tj * 64 + tx * 4 + qj;
            float re, im;
            unpack2(acc[qi][qj], re, im);
            P[i * CH + j] = make_float2(re, im);
        }
    }
}

// ---------------------------------------------------------------------------
// Finalize: reduce K-split partials, PLV = |G|/T, mirror.
// ---------------------------------------------------------------------------
__global__ void finalize_kernel(float* __restrict__ out) {
    const int idx = blockIdx.x * blockDim.x + threadIdx.x;
    if (idx >= BATCH * CH * CH) return;
    const int b  = idx >> 14;
    const int ij = idx & 16383;
    const int i  = ij >> 7;
    const int j  = ij & 127;
    if (i > j) return;
    float re = 0.0f, imv = 0.0f;
#pragma unroll
    for (int s = 0; s < KSPLIT; s++) {
        float2 g = g_part[(long long)(s * BATCH + b) * (CH * CH) + ij];
        re += g.x; imv += g.y;
    }
    const float plv = sqrtf(re * re + imv * imv) * (1.0f / (float)T_LEN);
    out[(b << 14) + (i << 7) + j] = plv;
    out[(b << 14) + (j << 7) + i] = plv;
}

// ---------------------------------------------------------------------------
extern "C" void kernel_launch(void* const* d_in, const int* in_sizes, int n_in,
                              void* d_out, int out_size) {
    const float* x = (const float*)d_in[0];
    float* out = (float*)d_out;

    const int smem_bytes = (T_LEN + HALF) * (int)sizeof(float2); // 96 KB
    cudaFuncSetAttribute(fft_kernel, cudaFuncAttributeMaxDynamicSharedMemorySize,
                         smem_bytes);

    fft_kernel<<<NSIG, 512, smem_bytes>>>(x);
    gram_kernel<<<dim3(KSPLIT, 3, BATCH), 256>>>();
    finalize_kernel<<<(BATCH * CH * CH + 255) / 256, 256>>>(out);
}